// round 15
// baseline (speedup 1.0000x reference)
#include <cuda_runtime.h>

// DelayBuffer: out[b, t, i*D + c] = emb[b, t - d_i, c] if t >= d_i else emb[b, t, c]
// d_i in (1, 2, 4, 8, 16, 32) = 1 << i
// B=4, S=4096, D=1024 (fp32). Output [B, S, 6*D].
//
// Converged gather structure (measured-best), with 256-bit evict-last input
// loads (sm_103a only allows L2::evict_last at .v4.b64/.v8.b32 width):
//   - block = 256 threads = two t-rows; each thread owns one 32 B chunk
//   - 6 front-batched ld.global.nc.L2::evict_last.v4.b64 (MLP=6, 192 B/thread
//     in flight), pinning the 64 MiB input in L2 against the store stream
//   - 12 streaming 16 B stores (__stcs, evict-first) into the contiguous
//     24 KiB output row

static constexpr int B  = 4;
static constexpr int S  = 4096;
static constexpr int D  = 1024;
static constexpr int ND = 6;       // number of delays
static constexpr int C8 = D / 8;   // 128 x 32B chunks per segment
static constexpr int ROW4 = ND * (D / 4);  // output row width in float4 (1536)

struct U64x4 { unsigned long long a, b, c, d; };

__device__ __forceinline__ U64x4 ldg_evict_last_256(const void* p) {
    U64x4 v;
    asm volatile("ld.global.nc.L2::evict_last.v4.b64 {%0,%1,%2,%3}, [%4];"
                 : "=l"(v.a), "=l"(v.b), "=l"(v.c), "=l"(v.d)
                 : "l"(p));
    return v;
}

__global__ __launch_bounds__(256, 8)
void delay_buffer_kernel(const float4* __restrict__ in, float4* __restrict__ out) {
    const int c8 = threadIdx.x & (C8 - 1);   // 0..127: which 32B chunk of the row
    const int j  = threadIdx.x >> 7;         // 0..1: which of the two rows
    const int t  = blockIdx.x * 2 + j;       // 0..4095
    const int b  = blockIdx.y;               // 0..3

    const float4* const ibat = in + (size_t)b * S * (D / 4);

    // 6 independent 32B loads, front-batched for MLP; pinned in L2
    U64x4 v[ND];
#pragma unroll
    for (int i = 0; i < ND; i++) {
        const int d = 1 << i;                     // DELAYS = (1,2,4,8,16,32)
        const int src_t = (t >= d) ? (t - d) : t;
        v[i] = ldg_evict_last_256(ibat + (size_t)src_t * (D / 4) + 2 * c8);
    }

    // streaming stores: each 32B chunk as two 16B evict-first stores
    float4* orow = out + (size_t)(b * S + t) * ROW4 + 2 * c8;
#pragma unroll
    for (int i = 0; i < ND; i++) {
        float4 lo, hi;
        lo.x = __ull2float_rz(0);  // placeholder, overwritten below via bit-cast
        // bit-cast the two 16B halves
        ((unsigned long long*)&lo)[0] = v[i].a;
        ((unsigned long long*)&lo)[1] = v[i].b;
        ((unsigned long long*)&hi)[0] = v[i].c;
        ((unsigned long long*)&hi)[1] = v[i].d;
        __stcs(orow + i * (D / 4) + 0, lo);
        __stcs(orow + i * (D / 4) + 1, hi);
    }
}

extern "C" void kernel_launch(void* const* d_in, const int* in_sizes, int n_in,
                              void* d_out, int out_size) {
    const float4* in = (const float4*)d_in[0];
    float4* out = (float4*)d_out;

    dim3 grid(S / 2, B);
    delay_buffer_kernel<<<grid, 256>>>(in, out);
}

// round 16
// speedup vs baseline: 1.5300x; 1.5300x over previous
#include <cuda_runtime.h>

// DelayBuffer: out[b, t, i*D + c] = emb[b, t - d_i, c] if t >= d_i else emb[b, t, c]
// d_i in (1, 2, 4, 8, 16, 32) = 1 << i
// B=4, S=4096, D=1024 (fp32). Output [B, S, 6*D].
//
// CONVERGED KERNEL (measured-best across 7 structural variants, all pinned
// at the ~5.9 TB/s practical HBM3e write-stream ceiling; see R9-R15 ledger):
//   - one 256-thread block per (b, t) output row
//   - 6 front-batched independent float4 loads (MLP=6) -> input re-reads
//     stay L2-resident (64 MiB input < 126 MiB L2)
//   - 6 streaming (evict-first) float4 stores into the contiguous 24 KiB
//     output row, protecting the input's L2 residency
// DRAM traffic == compulsory: 403 MB writes + 67 MB one-time read fill.

static constexpr int B  = 4;
static constexpr int S  = 4096;
static constexpr int D  = 1024;
static constexpr int D4 = D / 4;   // 256 float4 per segment
static constexpr int ND = 6;       // number of delays

__global__ __launch_bounds__(D4, 8)
void delay_buffer_kernel(const float4* __restrict__ in, float4* __restrict__ out) {
    const int c4 = threadIdx.x;    // 0..255 within a segment
    const int t  = blockIdx.x;     // 0..4095
    const int b  = blockIdx.y;     // 0..3

    // 6 independent loads, front-batched for MLP
    float4 v[ND];
#pragma unroll
    for (int i = 0; i < ND; i++) {
        const int d = 1 << i;                       // DELAYS = (1,2,4,8,16,32)
        const int src_t = (t >= d) ? (t - d) : t;
        v[i] = __ldg(&in[(b * S + src_t) * D4 + c4]);
    }

    // 6 streaming stores into the contiguous output row [row, 6*D]
    float4* orow = out + (size_t)(b * S + t) * (ND * D4) + c4;
#pragma unroll
    for (int i = 0; i < ND; i++) {
        __stcs(orow + i * D4, v[i]);
    }
}

extern "C" void kernel_launch(void* const* d_in, const int* in_sizes, int n_in,
                              void* d_out, int out_size) {
    const float4* in = (const float4*)d_in[0];
    float4* out = (float4*)d_out;

    dim3 grid(S, B);
    delay_buffer_kernel<<<grid, D4>>>(in, out);
}